// round 12
// baseline (speedup 1.0000x reference)
#include <cuda_runtime.h>
#include <cuda_fp16.h>
#include <math.h>

#define H 64
#define HNUM 256
#define NMAX 100000
#define EMAX 1200000
#define NEG_SLOPE 0.2f
#define CAP 128

// ---------------- scratch (static device globals) ----------------
__device__ __half g_h[(size_t)NMAX * H];    // fp16 hidden features (gather-heavy)
__device__ float g_out[(size_t)NMAX * H];
__device__ float4 g_xa[NMAX];               // packed {x0,x1,x2,as} per node
__device__ float g_ad[NMAX];
__device__ float g_as[NMAX];
__device__ float g_as2[NMAX];               // layer-0 folded attention scalars
__device__ float g_ad2[NMAX];
__device__ int   g_deg[NMAX];               // consume-and-reset each call
__device__ int   g_st[NMAX];
__device__ int   g_en[NMAX];
__device__ int   g_cur[NMAX];
__device__ int   g_total;
__device__ int   g_ssrc[EMAX];
__device__ float g_vn[(HNUM + 1) * H];      // rows 0..255 vn_direct, row 256 vn_root
__device__ float g_vntmp[HNUM * H];
__device__ float g_uv[4 * H];
__device__ float g_wc[3 * H];               // W_in @ W_l0  (3x64)
__device__ float g_cc[H];                   // (b_in + vn_emb) @ W_l0
__device__ float g_ps[8];                   // folded l0 attention coeffs

// ---------------- setup: hist + folded params + vn init + vntmp zero + packed xa/ad ----------
__global__ void k_setup(const float* __restrict__ x,
                        const int* __restrict__ ei,
                        const float* __restrict__ w_in,
                        const float* __restrict__ a_src_in,
                        const float* __restrict__ a_dst_in,
                        const float* __restrict__ b_in,
                        const float* __restrict__ w_l,
                        const float* __restrict__ a_src_l,
                        const float* __restrict__ a_dst_l,
                        float* __restrict__ uv,
                        float* __restrict__ wc, float* __restrict__ cc,
                        float* __restrict__ ps,
                        float* __restrict__ vn, float* __restrict__ vntmp,
                        const float* __restrict__ emb,
                        float4* __restrict__ xa, float* __restrict__ ad_,
                        int* __restrict__ deg,
                        int* total, int n, int E, int nblocks_node) {
    int b = blockIdx.x, t = threadIdx.x;
    if (b == 0) {
        if (t == 0) *total = 0;
        int l = t >> 7;
        int isdst = (t >> 6) & 1;
        int j = t & 63;
        const float* a = isdst ? (a_dst_l + l * H) : (a_src_l + l * H);
        const float* W = w_l + l * H * H;
        float s = 0.f;
        #pragma unroll 8
        for (int k = 0; k < H; k++) s += W[j * H + k] * a[k];
        uv[(l * 2 + isdst) * H + j] = s;
    } else if (b == 1) {
        __shared__ float sWc[3 * H];
        __shared__ float sCc[H];
        if (t < 192) {
            int i = t >> 6, j = t & 63;
            float s = 0.f;
            #pragma unroll 8
            for (int k = 0; k < H; k++) s += w_in[i * H + k] * w_l[k * H + j];
            sWc[t] = s;
            wc[t] = s;
        } else {
            int j = t - 192;
            float s = 0.f;
            #pragma unroll 8
            for (int k = 0; k < H; k++) s += (b_in[k] + emb[k]) * w_l[k * H + j];
            sCc[j] = s;
            cc[j] = s;
        }
        __syncthreads();
        if (t < 8) {
            int isdst = t >> 2, c = t & 3;
            const float* a = isdst ? a_dst_l : a_src_l;   // layer 0
            float s = 0.f;
            if (c < 3) {
                #pragma unroll 8
                for (int m = 0; m < H; m++) s += sWc[c * H + m] * a[m];
            } else {
                #pragma unroll 8
                for (int m = 0; m < H; m++) s += sCc[m] * a[m];
            }
            ps[isdst * 4 + c] = s;
        }
    } else if (b <= 66) {
        int i = (b - 2) * 256 + t;
        if (i < (HNUM + 1) * H) vn[i] = emb[i & (H - 1)];
    } else if (b <= 130) {
        int i = (b - 67) * 256 + t;
        if (i < HNUM * H) vntmp[i] = 0.f;
    } else if (b <= 130 + nblocks_node) {
        __shared__ float swa[6];
        if (t < 6) {
            int i = t % 3;
            const float* av = (t >= 3) ? a_dst_in : a_src_in;
            float s2 = 0.f;
            #pragma unroll 8
            for (int k = 0; k < H; k++) s2 += w_in[i * H + k] * av[k];
            swa[t] = s2;
        }
        __syncthreads();
        int i = (b - 131) * 256 + t;
        if (i < n) {
            float x0 = x[3 * i], x1 = x[3 * i + 1], x2 = x[3 * i + 2];
            xa[i] = make_float4(x0, x1, x2,
                                x0 * swa[0] + x1 * swa[1] + x2 * swa[2]);
            ad_[i] = x0 * swa[3] + x1 * swa[4] + x2 * swa[5];
        }
    } else {
        int i = (b - 131 - nblocks_node) * 256 + t;
        if (i < E) atomicAdd(&deg[ei[E + i]], 1);
    }
}

// ---------------- CSR alloc + ILP-4 scatter ----------------
__global__ __launch_bounds__(256) void k_alloc(int* __restrict__ deg,
                                               int* __restrict__ st,
                                               int* __restrict__ en,
                                               int* __restrict__ cur,
                                               int* total, int n) {
    __shared__ int sWarp[8];
    __shared__ int sBase;
    int t = threadIdx.x, lane = t & 31, w = t >> 5;
    int i = blockIdx.x * 256 + t;
    int d = 0;
    if (i < n) { d = deg[i]; deg[i] = 0; }   // reset for next call; self-loop implicit
    int x = d;
    #pragma unroll
    for (int o = 1; o < 32; o <<= 1) {
        int y = __shfl_up_sync(0xffffffffu, x, o);
        if (lane >= o) x += y;
    }
    if (lane == 31) sWarp[w] = x;
    __syncthreads();
    if (t == 0) {
        int s = 0;
        #pragma unroll
        for (int k = 0; k < 8; k++) { int v = sWarp[k]; sWarp[k] = s; s += v; }
        sBase = atomicAdd(total, s);
    }
    __syncthreads();
    int start = sBase + sWarp[w] + x - d;
    if (i < n) { st[i] = start; cur[i] = start; en[i] = start + d; }
}

__global__ void k_scatter(const int* __restrict__ ei, int* cur,
                          int* __restrict__ ssrc, int E) {
    int base = blockIdx.x * 1024 + threadIdx.x;
    #pragma unroll
    for (int k = 0; k < 4; k++) {
        int i = base + k * 256;
        if (i < E) {
            int s = ei[i], d = ei[E + i];
            int pos = atomicAdd(&cur[d], 1);
            ssrc[pos] = s;
        }
    }
}

// ---------------- fused layer-1 GAT + layer-0 GEMM, QUAD-PER-NODE, online softmax ----------
__global__ __launch_bounds__(256) void k_gat_in(
    const float4* __restrict__ xa,
    const float* __restrict__ ad_,
    const int* __restrict__ st, const int* __restrict__ en,
    const int* __restrict__ ssrc,
    const float* __restrict__ wc, const float* __restrict__ cc,
    const float* __restrict__ ps,
    __half* __restrict__ hout,
    float* __restrict__ as2, float* __restrict__ ad2, int n) {
    __shared__ float sWc[3 * H];
    __shared__ float sCc[H];
    __shared__ float sP[8];
    int t = threadIdx.x;
    if (t < 3 * H) sWc[t] = wc[t];
    if (t >= 192 && t < 192 + H) sCc[t - 192] = cc[t - 192];
    if (t < 8) sP[t] = ps[t];
    __syncthreads();
    int node = blockIdx.x * 64 + (t >> 2);
    int sub  = t & 3;
    if (node >= n) return;
    int s0 = st[node], e0 = en[node];
    float adn = ad_[node];

    float m, den, a0, a1, a2;
    if (sub == 0) {
        float4 xs = xa[node];
        float aself = xs.w + adn;
        aself = aself > 0.f ? aself : NEG_SLOPE * aself;
        m = aself; den = 1.f;
        a0 = xs.x; a1 = xs.y; a2 = xs.z;
    } else {
        m = -INFINITY; den = 0.f; a0 = a1 = a2 = 0.f;
    }

    for (int e = s0 + sub; e < e0; e += 4) {
        int s = ssrc[e];
        float4 v = xa[s];                     // single 16B load: x + as
        float a = v.w + adn;
        a = a > 0.f ? a : NEG_SLOPE * a;
        float newm = fmaxf(m, a);
        float sc = (m >= newm) ? 1.f : __expf(m - newm);
        float ex = __expf(a - newm);
        den = den * sc + ex;
        a0  = a0  * sc + ex * v.x;
        a1  = a1  * sc + ex * v.y;
        a2  = a2  * sc + ex * v.z;
        m = newm;
    }

    #pragma unroll
    for (int off = 1; off <= 2; off <<= 1) {
        float om   = __shfl_xor_sync(0xffffffffu, m,   off);
        float oden = __shfl_xor_sync(0xffffffffu, den, off);
        float oa0  = __shfl_xor_sync(0xffffffffu, a0,  off);
        float oa1  = __shfl_xor_sync(0xffffffffu, a1,  off);
        float oa2  = __shfl_xor_sync(0xffffffffu, a2,  off);
        float newm = fmaxf(m, om);
        float sc  = (m  >= newm) ? 1.f : __expf(m  - newm);
        float osc = (om >= newm) ? 1.f : __expf(om - newm);
        den = den * sc + oden * osc;
        a0  = a0  * sc + oa0  * osc;
        a1  = a1  * sc + oa1  * osc;
        a2  = a2  * sc + oa2  * osc;
        m = newm;
    }

    float inv = 1.f / den;
    a0 *= inv; a1 *= inv; a2 *= inv;

    __half2 hh[8];
    int cbase = sub * 16;
    #pragma unroll
    for (int k = 0; k < 16; k += 2) {
        int c = cbase + k;
        float h0 = a0 * sWc[c]     + a1 * sWc[H + c]     + a2 * sWc[2 * H + c]     + sCc[c];
        float h1 = a0 * sWc[c + 1] + a1 * sWc[H + c + 1] + a2 * sWc[2 * H + c + 1] + sCc[c + 1];
        hh[k >> 1] = __floats2half2_rn(h0, h1);
    }
    uint4* dst = (uint4*)(hout + (size_t)node * H + cbase);
    dst[0] = ((uint4*)hh)[0];
    dst[1] = ((uint4*)hh)[1];

    if (sub == 0) {
        as2[node] = a0 * sP[0] + a1 * sP[1] + a2 * sP[2] + sP[3];
        ad2[node] = a0 * sP[4] + a1 * sP[5] + a2 * sP[6] + sP[7];
    }
}

// ---------------- hidden-layer GEMM: Hout(fp16) = (A + vn[hb]) @ W, plus as/ad ----------------
__global__ __launch_bounds__(256) void k_gemm64(
    const float* __restrict__ A, const float* __restrict__ W,
    const float* __restrict__ u, const float* __restrict__ v,
    const float* __restrict__ vn, const int* __restrict__ hb,
    __half* __restrict__ Hout, float* __restrict__ as_, float* __restrict__ ad_,
    int n) {
    __shared__ __align__(16) float sW[H * H];
    __shared__ float sA[64 * 65];
    int t = threadIdx.x;
    for (int i = t; i < H * H; i += 256) sW[i] = W[i];
    int block_row = blockIdx.x * 64;
    for (int i = t; i < 64 * H; i += 256) {
        int r = i >> 6, c = i & 63;
        int node = block_row + r;
        float val = 0.f;
        if (node < n) val = A[(size_t)node * H + c] + vn[hb[node] * H + c];
        sA[r * 65 + c] = val;
    }
    __syncthreads();
    int ty = t >> 4, tx = t & 15;
    float acc[4][4] = {};
    #pragma unroll 8
    for (int k = 0; k < H; k++) {
        float a0 = sA[(ty * 4 + 0) * 65 + k];
        float a1 = sA[(ty * 4 + 1) * 65 + k];
        float a2 = sA[(ty * 4 + 2) * 65 + k];
        float a3 = sA[(ty * 4 + 3) * 65 + k];
        float4 w4 = *(const float4*)&sW[k * H + tx * 4];
        acc[0][0] += a0 * w4.x; acc[0][1] += a0 * w4.y; acc[0][2] += a0 * w4.z; acc[0][3] += a0 * w4.w;
        acc[1][0] += a1 * w4.x; acc[1][1] += a1 * w4.y; acc[1][2] += a1 * w4.z; acc[1][3] += a1 * w4.w;
        acc[2][0] += a2 * w4.x; acc[2][1] += a2 * w4.y; acc[2][2] += a2 * w4.z; acc[2][3] += a2 * w4.w;
        acc[3][0] += a3 * w4.x; acc[3][1] += a3 * w4.y; acc[3][2] += a3 * w4.z; acc[3][3] += a3 * w4.w;
    }
    #pragma unroll
    for (int i = 0; i < 4; i++) {
        int node = block_row + ty * 4 + i;
        if (node < n) {
            union { uint2 u2; __half2 h2[2]; } pk;
            pk.h2[0] = __floats2half2_rn(acc[i][0], acc[i][1]);
            pk.h2[1] = __floats2half2_rn(acc[i][2], acc[i][3]);
            *(uint2*)&Hout[(size_t)node * H + tx * 4] = pk.u2;
        }
    }
    if (t < 64) {
        int node = block_row + t;
        if (node < n) {
            float s = 0.f, d = 0.f;
            #pragma unroll 8
            for (int k = 0; k < H; k++) {
                float a = sA[t * 65 + k];
                s += a * u[k];
                d += a * v[k];
            }
            as_[node] = s;
            ad_[node] = d;
        }
    }
}

// ---------------- hidden GAT: fp16 h gather, parity-split lanes (2 edges/iter) ----
__global__ __launch_bounds__(256) void k_gat(
    const __half2* __restrict__ h2,
    const float* __restrict__ as_, const float* __restrict__ ad_,
    const int* __restrict__ st, const int* __restrict__ en,
    const int* __restrict__ ssrc,
    const float* __restrict__ bias,
    float* __restrict__ out,
    float* __restrict__ vntmp, const int* __restrict__ hb, int n) {
    __shared__ int   s_src[8][CAP];
    __shared__ float s_w[8][CAP];
    int t = threadIdx.x, lane = t & 31, w = t >> 5;
    int node = blockIdx.x * 8 + w;
    if (node >= n) return;
    int start = st[node], end = en[node];
    int deg = end - start;
    float adn = ad_[node];
    float aself = as_[node] + adn;
    aself = aself > 0.f ? aself : NEG_SLOPE * aself;

    if (deg <= CAP) {
        // alpha pass + den
        float m = aself;
        for (int i = lane; i < deg; i += 32) {
            int s = ssrc[start + i];
            float a = as_[s] + adn;
            a = a > 0.f ? a : NEG_SLOPE * a;
            s_src[w][i] = s;
            s_w[w][i] = a;
            m = fmaxf(m, a);
        }
        #pragma unroll
        for (int o = 16; o; o >>= 1) m = fmaxf(m, __shfl_xor_sync(0xffffffffu, m, o));
        float wself = __expf(aself - m);
        float den = (lane == 0) ? wself : 0.f;
        for (int i = lane; i < deg; i += 32) {
            float ex = __expf(s_w[w][i] - m);
            s_w[w][i] = ex;
            den += ex;
        }
        #pragma unroll
        for (int o = 16; o; o >>= 1) den += __shfl_xor_sync(0xffffffffu, den, o);
        __syncwarp();

        // parity-split aggregation: lanes 0-15 even edges, 16-31 odd; 4 features/lane
        int half = lane >> 4, fl = lane & 15;
        float4 acc = make_float4(0.f, 0.f, 0.f, 0.f);
        if (half == 0) {
            uint2 raw = *(const uint2*)(h2 + ((size_t)node << 5) + fl * 2);
            float2 f0 = __half22float2(((const __half2*)&raw)[0]);
            float2 f1 = __half22float2(((const __half2*)&raw)[1]);
            acc.x = wself * f0.x; acc.y = wself * f0.y;
            acc.z = wself * f1.x; acc.w = wself * f1.y;
        }
        for (int j = half; j < deg; j += 2) {
            float wj = s_w[w][j];
            uint2 raw = *(const uint2*)(h2 + ((size_t)s_src[w][j] << 5) + fl * 2);
            float2 f0 = __half22float2(((const __half2*)&raw)[0]);
            float2 f1 = __half22float2(((const __half2*)&raw)[1]);
            acc.x += wj * f0.x; acc.y += wj * f0.y;
            acc.z += wj * f1.x; acc.w += wj * f1.y;
        }
        acc.x += __shfl_xor_sync(0xffffffffu, acc.x, 16);
        acc.y += __shfl_xor_sync(0xffffffffu, acc.y, 16);
        acc.z += __shfl_xor_sync(0xffffffffu, acc.z, 16);
        acc.w += __shfl_xor_sync(0xffffffffu, acc.w, 16);
        float inv = 1.f / den;
        if (half == 0) {
            float4 b4 = ((const float4*)bias)[fl];
            float4 o4 = make_float4(acc.x * inv + b4.x, acc.y * inv + b4.y,
                                    acc.z * inv + b4.z, acc.w * inv + b4.w);
            ((float4*)out)[(size_t)node * 16 + fl] = o4;
            if (vntmp) {
                int blk = hb[node];
                atomicAdd(&vntmp[blk * H + fl * 4 + 0], o4.x);
                atomicAdd(&vntmp[blk * H + fl * 4 + 1], o4.y);
                atomicAdd(&vntmp[blk * H + fl * 4 + 2], o4.z);
                atomicAdd(&vntmp[blk * H + fl * 4 + 3], o4.w);
            }
        }
    } else {
        // rare fallback: global recompute, lane = 2 features
        float2 acc;
        float m = aself;
        for (int e = start + lane; e < end; e += 32) {
            float a = as_[ssrc[e]] + adn;
            a = a > 0.f ? a : NEG_SLOPE * a;
            m = fmaxf(m, a);
        }
        #pragma unroll
        for (int o = 16; o; o >>= 1) m = fmaxf(m, __shfl_xor_sync(0xffffffffu, m, o));
        float wself = __expf(aself - m);
        float denl = (lane == 0) ? wself : 0.f;
        {
            float2 hs = __half22float2(h2[((size_t)node << 5) + lane]);
            acc.x = wself * hs.x;
            acc.y = wself * hs.y;
        }
        for (int eb = start; eb < end; eb += 32) {
            int e = eb + lane;
            float ex = 0.f; int s = 0;
            if (e < end) {
                s = ssrc[e];
                float a = as_[s] + adn;
                a = a > 0.f ? a : NEG_SLOPE * a;
                ex = __expf(a - m);
            }
            denl += ex;
            int cnt = min(32, end - eb);
            for (int j = 0; j < cnt; j++) {
                float wj = __shfl_sync(0xffffffffu, ex, j);
                int sj   = __shfl_sync(0xffffffffu, s, j);
                float2 v = __half22float2(h2[((size_t)sj << 5) + lane]);
                acc.x += wj * v.x;
                acc.y += wj * v.y;
            }
        }
        float den = denl;
        #pragma unroll
        for (int o = 16; o; o >>= 1) den += __shfl_xor_sync(0xffffffffu, den, o);
        float inv = 1.f / den;
        float2 b = ((const float2*)bias)[lane];
        float2 o2 = make_float2(acc.x * inv + b.x, acc.y * inv + b.y);
        ((float2*)out)[(size_t)node * 32 + lane] = o2;
        if (vntmp) {
            int blk = hb[node];
            atomicAdd(&vntmp[blk * H + lane * 2],     o2.x);
            atomicAdd(&vntmp[blk * H + lane * 2 + 1], o2.y);
        }
    }
}

// ---------------- fused vn update + both MLPs ----------------
__global__ __launch_bounds__(256) void k_vn_mlp2(
    float* vn, const float* __restrict__ vn_tmp,
    const float* __restrict__ mw1, const float* __restrict__ mb1,
    const float* __restrict__ mw2, const float* __restrict__ mb2, int rows) {
    __shared__ __align__(16) float sW[H * H];
    __shared__ float sV[64 * 65];
    __shared__ float sRoot[H];
    __shared__ float sColNew[H];
    __shared__ float red[4][H];
    int t = threadIdx.x;
    int r0 = blockIdx.x * 64;

    if (t < H) sRoot[t] = vn[HNUM * H + t];
    __syncthreads();
    {
        int c = t & 63, g = t >> 6;
        float s = 0.f;
        for (int r = g; r < HNUM; r += 4) s += vn[r * H + c] + vn_tmp[r * H + c];
        red[g][c] = s;
    }
    __syncthreads();
    if (t < H) sColNew[t] = red[0][t] + red[1][t] + red[2][t] + red[3][t] + 257.f * sRoot[t];
    __syncthreads();
    for (int i = t; i < 64 * H; i += 256) {
        int r = i >> 6, c = i & 63;
        int gr = r0 + r;
        float val = 0.f;
        if (gr < HNUM)      val = vn[gr * H + c] + vn_tmp[gr * H + c] + sRoot[c];
        else if (gr == HNUM) val = sColNew[c];
        sV[r * 65 + c] = val;
    }
    int ty = t >> 4, tx = t & 15;
    for (int m = 0; m < 2; m++) {
        const float* w1 = mw1 + m * H * H;
        const float* b1 = mb1 + m * H;
        const float* w2 = mw2 + m * H * H;
        const float* b2 = mb2 + m * H;
        for (int i = t; i < H * H; i += 256) sW[i] = w1[i];
        __syncthreads();
        float acc[4][4] = {};
        #pragma unroll 8
        for (int k = 0; k < H; k++) {
            float a0 = sV[(ty * 4 + 0) * 65 + k];
            float a1 = sV[(ty * 4 + 1) * 65 + k];
            float a2 = sV[(ty * 4 + 2) * 65 + k];
            float a3 = sV[(ty * 4 + 3) * 65 + k];
            float4 w4 = *(const float4*)&sW[k * H + tx * 4];
            acc[0][0] += a0 * w4.x; acc[0][1] += a0 * w4.y; acc[0][2] += a0 * w4.z; acc[0][3] += a0 * w4.w;
            acc[1][0] += a1 * w4.x; acc[1][1] += a1 * w4.y; acc[1][2] += a1 * w4.z; acc[1][3] += a1 * w4.w;
            acc[2][0] += a2 * w4.x; acc[2][1] += a2 * w4.y; acc[2][2] += a2 * w4.z; acc[2][3] += a2 * w4.w;
            acc[3][0] += a3 * w4.x; acc[3][1] += a3 * w4.y; acc[3][2] += a3 * w4.z; acc[3][3] += a3 * w4.w;
        }
        __syncthreads();
        #pragma unroll
        for (int i = 0; i < 4; i++)
            #pragma unroll
            for (int j = 0; j < 4; j++) {
                float vbl = acc[i][j] + b1[tx * 4 + j];
                sV[(ty * 4 + i) * 65 + tx * 4 + j] = vbl > 0.f ? vbl : 0.f;
            }
        for (int i = t; i < H * H; i += 256) sW[i] = w2[i];
        __syncthreads();
        float acc2[4][4] = {};
        #pragma unroll 8
        for (int k = 0; k < H; k++) {
            float a0 = sV[(ty * 4 + 0) * 65 + k];
            float a1 = sV[(ty * 4 + 1) * 65 + k];
            float a2 = sV[(ty * 4 + 2) * 65 + k];
            float a3 = sV[(ty * 4 + 3) * 65 + k];
            float4 w4 = *(const float4*)&sW[k * H + tx * 4];
            acc2[0][0] += a0 * w4.x; acc2[0][1] += a0 * w4.y; acc2[0][2] += a0 * w4.z; acc2[0][3] += a0 * w4.w;
            acc2[1][0] += a1 * w4.x; acc2[1][1] += a1 * w4.y; acc2[1][2] += a1 * w4.z; acc2[1][3] += a1 * w4.w;
            acc2[2][0] += a2 * w4.x; acc2[2][1] += a2 * w4.y; acc2[2][2] += a2 * w4.z; acc2[2][3] += a2 * w4.w;
            acc2[3][0] += a3 * w4.x; acc2[3][1] += a3 * w4.y; acc2[3][2] += a3 * w4.z; acc2[3][3] += a3 * w4.w;
        }
        __syncthreads();
        #pragma unroll
        for (int i = 0; i < 4; i++)
            #pragma unroll
            for (int j = 0; j < 4; j++) {
                float vbl = acc2[i][j] + b2[tx * 4 + j];
                sV[(ty * 4 + i) * 65 + tx * 4 + j] = vbl > 0.f ? vbl : 0.f;
            }
        __syncthreads();
    }
    for (int i = t; i < 64 * H; i += 256) {
        int r = i >> 6, c = i & 63;
        if (r0 + r < rows) vn[(r0 + r) * H + c] = sV[r * 65 + c];
    }
}

// ---------------- host launch ----------------
extern "C" void kernel_launch(void* const* d_in, const int* in_sizes, int n_in,
                              void* d_out, int out_size) {
    const float* x  = (const float*)d_in[0];
    const int*   ei = (const int*)d_in[1];
    const int*   hb = (const int*)d_in[2];
    int base = (n_in >= 18) ? 5 : 4;
    const float* w_in     = (const float*)d_in[base + 0];
    const float* a_src_in = (const float*)d_in[base + 1];
    const float* a_dst_in = (const float*)d_in[base + 2];
    const float* b_in     = (const float*)d_in[base + 3];
    const float* w_l      = (const float*)d_in[base + 4];
    const float* a_src_l  = (const float*)d_in[base + 5];
    const float* a_dst_l  = (const float*)d_in[base + 6];
    const float* b_l      = (const float*)d_in[base + 7];
    const float* mw1      = (const float*)d_in[base + 8];
    const float* mb1      = (const float*)d_in[base + 9];
    const float* mw2      = (const float*)d_in[base + 10];
    const float* mb2      = (const float*)d_in[base + 11];
    const float* vne      = (const float*)d_in[base + 12];

    int N = in_sizes[0] / 3;
    int E = in_sizes[1] / 2;

    float *pout, *pas, *pad, *pas2, *pad2, *pvn, *pvntmp, *puv, *pwc, *pcc, *pps;
    float4* pxa;
    __half* ph;
    int *pdeg, *pst, *pen, *pcur, *pssrc, *ptotal;
    cudaGetSymbolAddress((void**)&ph, g_h);
    cudaGetSymbolAddress((void**)&pout, g_out);
    cudaGetSymbolAddress((void**)&pxa, g_xa);
    cudaGetSymbolAddress((void**)&pas, g_as);
    cudaGetSymbolAddress((void**)&pad, g_ad);
    cudaGetSymbolAddress((void**)&pas2, g_as2);
    cudaGetSymbolAddress((void**)&pad2, g_ad2);
    cudaGetSymbolAddress((void**)&pdeg, g_deg);
    cudaGetSymbolAddress((void**)&pst, g_st);
    cudaGetSymbolAddress((void**)&pen, g_en);
    cudaGetSymbolAddress((void**)&pcur, g_cur);
    cudaGetSymbolAddress((void**)&pssrc, g_ssrc);
    cudaGetSymbolAddress((void**)&ptotal, g_total);
    cudaGetSymbolAddress((void**)&pvn, g_vn);
    cudaGetSymbolAddress((void**)&pvntmp, g_vntmp);
    cudaGetSymbolAddress((void**)&puv, g_uv);
    cudaGetSymbolAddress((void**)&pwc, g_wc);
    cudaGetSymbolAddress((void**)&pcc, g_cc);
    cudaGetSymbolAddress((void**)&pps, g_ps);

    int nwarp_blocks = (N + 7) / 8;
    int gemm_blocks  = (N + 63) / 64;
    int nblocks_node = (N + 255) / 256;
    int nblocks_edge = (E + 255) / 256;
    int setup_blocks = 131 + nblocks_node + nblocks_edge;

    // 0: setup (hist + folded params + vn init + vntmp zero + packed xa/ad)
    k_setup<<<setup_blocks, 256>>>(x, ei, w_in, a_src_in, a_dst_in, b_in,
                                   w_l, a_src_l, a_dst_l,
                                   puv, pwc, pcc, pps,
                                   pvn, pvntmp, vne, pxa, pad, pdeg,
                                   ptotal, N, E, nblocks_node);
    // 1-2: CSR alloc + ILP-4 scatter
    k_alloc<<<nblocks_node, 256>>>(pdeg, pst, pen, pcur, ptotal, N);
    k_scatter<<<(E + 1023) / 1024, 256>>>(ei, pcur, pssrc, E);

    // 3: fused input GAT + layer-0 GEMM, quad-per-node online softmax, packed xa
    k_gat_in<<<(N + 63) / 64, 256>>>(pxa, pad, pst, pen, pssrc,
                                     pwc, pcc, pps, ph, pas2, pad2, N);
    // 4: layer-0 GAT (with fused vn segsum)
    k_gat<<<nwarp_blocks, 256>>>((const __half2*)ph, pas2, pad2, pst, pen, pssrc,
                                 b_l, pout, pvntmp, hb, N);
    // 5: fused vn update + both MLPs
    k_vn_mlp2<<<(HNUM + 1 + 63) / 64, 256>>>(pvn, pvntmp, mw1, mb1, mw2, mb2, HNUM + 1);

    // 6-7: l = 1 (trailing vn updates are dead code w.r.t. output)
    k_gemm64<<<gemm_blocks, 256>>>(pout, w_l + H * H, puv + 2 * H, puv + 3 * H,
                                   pvn, hb, ph, pas, pad, N);
    k_gat<<<nwarp_blocks, 256>>>((const __half2*)ph, pas, pad, pst, pen, pssrc,
                                 b_l + H, (float*)d_out, nullptr, nullptr, N);
}

// round 13
// speedup vs baseline: 1.4188x; 1.4188x over previous
#include <cuda_runtime.h>
#include <cuda_fp16.h>
#include <math.h>

#define H 64
#define HNUM 256
#define NMAX 100000
#define EMAX 1200000
#define NEG_SLOPE 0.2f
#define CAP 128

// ---------------- scratch (static device globals) ----------------
__device__ __half g_h[(size_t)NMAX * H];    // fp16 hidden features (gather-heavy)
__device__ float g_out[(size_t)NMAX * H];
__device__ float4 g_xa[NMAX];               // packed {x0,x1,x2,as} per node
__device__ float g_ad[NMAX];
__device__ float g_as[NMAX];
__device__ float g_as2[NMAX];               // layer-0 folded attention scalars
__device__ float g_ad2[NMAX];
__device__ int   g_deg[NMAX];               // consume-and-reset each call
__device__ int   g_st[NMAX];
__device__ int   g_en[NMAX];
__device__ int   g_cur[NMAX];
__device__ int   g_total;
__device__ int   g_ssrc[EMAX];
__device__ float g_vn[(HNUM + 1) * H];      // rows 0..255 vn_direct, row 256 vn_root
__device__ float g_vntmp[HNUM * H];
__device__ float g_uv[4 * H];
__device__ float g_wc[3 * H];               // W_in @ W_l0  (3x64)
__device__ float g_cc[H];                   // (b_in + vn_emb) @ W_l0
__device__ float g_ps[8];                   // folded l0 attention coeffs

// ---------------- setup: hist + folded params + vn init + vntmp zero + packed xa/ad ----------
__global__ void k_setup(const float* __restrict__ x,
                        const int* __restrict__ ei,
                        const float* __restrict__ w_in,
                        const float* __restrict__ a_src_in,
                        const float* __restrict__ a_dst_in,
                        const float* __restrict__ b_in,
                        const float* __restrict__ w_l,
                        const float* __restrict__ a_src_l,
                        const float* __restrict__ a_dst_l,
                        float* __restrict__ uv,
                        float* __restrict__ wc, float* __restrict__ cc,
                        float* __restrict__ ps,
                        float* __restrict__ vn, float* __restrict__ vntmp,
                        const float* __restrict__ emb,
                        float4* __restrict__ xa, float* __restrict__ ad_,
                        int* __restrict__ deg,
                        int* total, int n, int E, int nblocks_node) {
    int b = blockIdx.x, t = threadIdx.x;
    if (b == 0) {
        if (t == 0) *total = 0;
        int l = t >> 7;
        int isdst = (t >> 6) & 1;
        int j = t & 63;
        const float* a = isdst ? (a_dst_l + l * H) : (a_src_l + l * H);
        const float* W = w_l + l * H * H;
        float s = 0.f;
        #pragma unroll 8
        for (int k = 0; k < H; k++) s += W[j * H + k] * a[k];
        uv[(l * 2 + isdst) * H + j] = s;
    } else if (b == 1) {
        __shared__ float sWc[3 * H];
        __shared__ float sCc[H];
        if (t < 192) {
            int i = t >> 6, j = t & 63;
            float s = 0.f;
            #pragma unroll 8
            for (int k = 0; k < H; k++) s += w_in[i * H + k] * w_l[k * H + j];
            sWc[t] = s;
            wc[t] = s;
        } else {
            int j = t - 192;
            float s = 0.f;
            #pragma unroll 8
            for (int k = 0; k < H; k++) s += (b_in[k] + emb[k]) * w_l[k * H + j];
            sCc[j] = s;
            cc[j] = s;
        }
        __syncthreads();
        if (t < 8) {
            int isdst = t >> 2, c = t & 3;
            const float* a = isdst ? a_dst_l : a_src_l;   // layer 0
            float s = 0.f;
            if (c < 3) {
                #pragma unroll 8
                for (int m = 0; m < H; m++) s += sWc[c * H + m] * a[m];
            } else {
                #pragma unroll 8
                for (int m = 0; m < H; m++) s += sCc[m] * a[m];
            }
            ps[isdst * 4 + c] = s;
        }
    } else if (b <= 66) {
        int i = (b - 2) * 256 + t;
        if (i < (HNUM + 1) * H) vn[i] = emb[i & (H - 1)];
    } else if (b <= 130) {
        int i = (b - 67) * 256 + t;
        if (i < HNUM * H) vntmp[i] = 0.f;
    } else if (b <= 130 + nblocks_node) {
        __shared__ float swa[6];
        if (t < 6) {
            int i = t % 3;
            const float* av = (t >= 3) ? a_dst_in : a_src_in;
            float s2 = 0.f;
            #pragma unroll 8
            for (int k = 0; k < H; k++) s2 += w_in[i * H + k] * av[k];
            swa[t] = s2;
        }
        __syncthreads();
        int i = (b - 131) * 256 + t;
        if (i < n) {
            float x0 = x[3 * i], x1 = x[3 * i + 1], x2 = x[3 * i + 2];
            xa[i] = make_float4(x0, x1, x2,
                                x0 * swa[0] + x1 * swa[1] + x2 * swa[2]);
            ad_[i] = x0 * swa[3] + x1 * swa[4] + x2 * swa[5];
        }
    } else {
        int i = (b - 131 - nblocks_node) * 256 + t;
        if (i < E) atomicAdd(&deg[ei[E + i]], 1);
    }
}

// ---------------- CSR alloc + ILP-4 scatter ----------------
__global__ __launch_bounds__(256) void k_alloc(int* __restrict__ deg,
                                               int* __restrict__ st,
                                               int* __restrict__ en,
                                               int* __restrict__ cur,
                                               int* total, int n) {
    __shared__ int sWarp[8];
    __shared__ int sBase;
    int t = threadIdx.x, lane = t & 31, w = t >> 5;
    int i = blockIdx.x * 256 + t;
    int d = 0;
    if (i < n) { d = deg[i]; deg[i] = 0; }   // reset for next call; self-loop implicit
    int x = d;
    #pragma unroll
    for (int o = 1; o < 32; o <<= 1) {
        int y = __shfl_up_sync(0xffffffffu, x, o);
        if (lane >= o) x += y;
    }
    if (lane == 31) sWarp[w] = x;
    __syncthreads();
    if (t == 0) {
        int s = 0;
        #pragma unroll
        for (int k = 0; k < 8; k++) { int v = sWarp[k]; sWarp[k] = s; s += v; }
        sBase = atomicAdd(total, s);
    }
    __syncthreads();
    int start = sBase + sWarp[w] + x - d;
    if (i < n) { st[i] = start; cur[i] = start; en[i] = start + d; }
}

__global__ void k_scatter(const int* __restrict__ ei, int* cur,
                          int* __restrict__ ssrc, int E) {
    int base = blockIdx.x * 1024 + threadIdx.x;
    #pragma unroll
    for (int k = 0; k < 4; k++) {
        int i = base + k * 256;
        if (i < E) {
            int s = ei[i], d = ei[E + i];
            int pos = atomicAdd(&cur[d], 1);
            ssrc[pos] = s;
        }
    }
}

// ---------------- fused layer-1 GAT + layer-0 GEMM, QUAD-PER-NODE, online softmax ----------
// One LDG.128 per edge via packed xa = {x0,x1,x2,as}.
__global__ __launch_bounds__(256) void k_gat_in(
    const float4* __restrict__ xa,
    const float* __restrict__ ad_,
    const int* __restrict__ st, const int* __restrict__ en,
    const int* __restrict__ ssrc,
    const float* __restrict__ wc, const float* __restrict__ cc,
    const float* __restrict__ ps,
    __half* __restrict__ hout,
    float* __restrict__ as2, float* __restrict__ ad2, int n) {
    __shared__ float sWc[3 * H];
    __shared__ float sCc[H];
    __shared__ float sP[8];
    int t = threadIdx.x;
    if (t < 3 * H) sWc[t] = wc[t];
    if (t >= 192 && t < 192 + H) sCc[t - 192] = cc[t - 192];
    if (t < 8) sP[t] = ps[t];
    __syncthreads();
    int node = blockIdx.x * 64 + (t >> 2);
    int sub  = t & 3;
    if (node >= n) return;
    int s0 = st[node], e0 = en[node];
    float adn = ad_[node];

    // per-lane online-softmax state; sub0 seeds with the implicit self loop
    float m, den, a0, a1, a2;
    if (sub == 0) {
        float4 xs = xa[node];
        float aself = xs.w + adn;
        aself = aself > 0.f ? aself : NEG_SLOPE * aself;
        m = aself; den = 1.f;
        a0 = xs.x; a1 = xs.y; a2 = xs.z;
    } else {
        m = -INFINITY; den = 0.f; a0 = a1 = a2 = 0.f;
    }

    for (int e = s0 + sub; e < e0; e += 4) {
        int s = ssrc[e];
        float4 v = xa[s];                     // single 16B load: x + as
        float a = v.w + adn;
        a = a > 0.f ? a : NEG_SLOPE * a;
        float newm = fmaxf(m, a);
        float sc = (m >= newm) ? 1.f : __expf(m - newm);
        float ex = __expf(a - newm);
        den = den * sc + ex;
        a0  = a0  * sc + ex * v.x;
        a1  = a1  * sc + ex * v.y;
        a2  = a2  * sc + ex * v.z;
        m = newm;
    }

    // xor-butterfly merge of 4 partial softmax states (guards avoid -inf NaNs)
    #pragma unroll
    for (int off = 1; off <= 2; off <<= 1) {
        float om   = __shfl_xor_sync(0xffffffffu, m,   off);
        float oden = __shfl_xor_sync(0xffffffffu, den, off);
        float oa0  = __shfl_xor_sync(0xffffffffu, a0,  off);
        float oa1  = __shfl_xor_sync(0xffffffffu, a1,  off);
        float oa2  = __shfl_xor_sync(0xffffffffu, a2,  off);
        float newm = fmaxf(m, om);
        float sc  = (m  >= newm) ? 1.f : __expf(m  - newm);
        float osc = (om >= newm) ? 1.f : __expf(om - newm);
        den = den * sc + oden * osc;
        a0  = a0  * sc + oa0  * osc;
        a1  = a1  * sc + oa1  * osc;
        a2  = a2  * sc + oa2  * osc;
        m = newm;
    }

    float inv = 1.f / den;
    a0 *= inv; a1 *= inv; a2 *= inv;

    // GEMV: each lane computes its 16 of 64 columns; 32B store per lane
    __half2 hh[8];
    int cbase = sub * 16;
    #pragma unroll
    for (int k = 0; k < 16; k += 2) {
        int c = cbase + k;
        float h0 = a0 * sWc[c]     + a1 * sWc[H + c]     + a2 * sWc[2 * H + c]     + sCc[c];
        float h1 = a0 * sWc[c + 1] + a1 * sWc[H + c + 1] + a2 * sWc[2 * H + c + 1] + sCc[c + 1];
        hh[k >> 1] = __floats2half2_rn(h0, h1);
    }
    uint4* dst = (uint4*)(hout + (size_t)node * H + cbase);
    dst[0] = ((uint4*)hh)[0];
    dst[1] = ((uint4*)hh)[1];

    if (sub == 0) {
        as2[node] = a0 * sP[0] + a1 * sP[1] + a2 * sP[2] + sP[3];
        ad2[node] = a0 * sP[4] + a1 * sP[5] + a2 * sP[6] + sP[7];
    }
}

// ---------------- hidden-layer GEMM: Hout(fp16) = (A + vn[hb]) @ W, plus as/ad ----------------
__global__ __launch_bounds__(256) void k_gemm64(
    const float* __restrict__ A, const float* __restrict__ W,
    const float* __restrict__ u, const float* __restrict__ v,
    const float* __restrict__ vn, const int* __restrict__ hb,
    __half* __restrict__ Hout, float* __restrict__ as_, float* __restrict__ ad_,
    int n) {
    __shared__ __align__(16) float sW[H * H];
    __shared__ float sA[64 * 65];
    int t = threadIdx.x;
    for (int i = t; i < H * H; i += 256) sW[i] = W[i];
    int block_row = blockIdx.x * 64;
    for (int i = t; i < 64 * H; i += 256) {
        int r = i >> 6, c = i & 63;
        int node = block_row + r;
        float val = 0.f;
        if (node < n) val = A[(size_t)node * H + c] + vn[hb[node] * H + c];
        sA[r * 65 + c] = val;
    }
    __syncthreads();
    int ty = t >> 4, tx = t & 15;
    float acc[4][4] = {};
    #pragma unroll 8
    for (int k = 0; k < H; k++) {
        float a0 = sA[(ty * 4 + 0) * 65 + k];
        float a1 = sA[(ty * 4 + 1) * 65 + k];
        float a2 = sA[(ty * 4 + 2) * 65 + k];
        float a3 = sA[(ty * 4 + 3) * 65 + k];
        float4 w4 = *(const float4*)&sW[k * H + tx * 4];
        acc[0][0] += a0 * w4.x; acc[0][1] += a0 * w4.y; acc[0][2] += a0 * w4.z; acc[0][3] += a0 * w4.w;
        acc[1][0] += a1 * w4.x; acc[1][1] += a1 * w4.y; acc[1][2] += a1 * w4.z; acc[1][3] += a1 * w4.w;
        acc[2][0] += a2 * w4.x; acc[2][1] += a2 * w4.y; acc[2][2] += a2 * w4.z; acc[2][3] += a2 * w4.w;
        acc[3][0] += a3 * w4.x; acc[3][1] += a3 * w4.y; acc[3][2] += a3 * w4.z; acc[3][3] += a3 * w4.w;
    }
    #pragma unroll
    for (int i = 0; i < 4; i++) {
        int node = block_row + ty * 4 + i;
        if (node < n) {
            union { uint2 u2; __half2 h2[2]; } pk;
            pk.h2[0] = __floats2half2_rn(acc[i][0], acc[i][1]);
            pk.h2[1] = __floats2half2_rn(acc[i][2], acc[i][3]);
            *(uint2*)&Hout[(size_t)node * H + tx * 4] = pk.u2;
        }
    }
    if (t < 64) {
        int node = block_row + t;
        if (node < n) {
            float s = 0.f, d = 0.f;
            #pragma unroll 8
            for (int k = 0; k < H; k++) {
                float a = sA[t * 65 + k];
                s += a * u[k];
                d += a * v[k];
            }
            as_[node] = s;
            ad_[node] = d;
        }
    }
}

// ---------------- hidden GAT: fp16 h gather, unroll-2 aggregation (+ opt segsum) ----
__global__ __launch_bounds__(256) void k_gat(
    const __half2* __restrict__ h2,
    const float* __restrict__ as_, const float* __restrict__ ad_,
    const int* __restrict__ st, const int* __restrict__ en,
    const int* __restrict__ ssrc,
    const float* __restrict__ bias,
    float* __restrict__ out,
    float* __restrict__ vntmp, const int* __restrict__ hb, int n) {
    __shared__ int   s_src[8][CAP];
    __shared__ float s_w[8][CAP];
    int t = threadIdx.x, lane = t & 31, w = t >> 5;
    int node = blockIdx.x * 8 + w;
    if (node >= n) return;
    int start = st[node], end = en[node];
    int deg = end - start;
    float adn = ad_[node];
    float aself = as_[node] + adn;
    aself = aself > 0.f ? aself : NEG_SLOPE * aself;
    float2 acc;
    float den;

    if (deg <= CAP) {
        float m = aself;
        for (int i = lane; i < deg; i += 32) {
            int s = ssrc[start + i];
            float a = as_[s] + adn;
            a = a > 0.f ? a : NEG_SLOPE * a;
            s_src[w][i] = s;
            s_w[w][i] = a;
            m = fmaxf(m, a);
        }
        #pragma unroll
        for (int o = 16; o; o >>= 1) m = fmaxf(m, __shfl_xor_sync(0xffffffffu, m, o));
        float wself = __expf(aself - m);
        den = (lane == 0) ? wself : 0.f;     // den IS lane-reduced -> count self once
        {
            float2 hs = __half22float2(h2[((size_t)node << 5) + lane]);
            acc.x = wself * hs.x;            // acc is per-lane features -> every lane
            acc.y = wself * hs.y;
        }
        for (int i = lane; i < deg; i += 32) {
            float ex = __expf(s_w[w][i] - m);
            s_w[w][i] = ex;
            den += ex;
        }
        #pragma unroll
        for (int o = 16; o; o >>= 1) den += __shfl_xor_sync(0xffffffffu, den, o);
        __syncwarp();
        float2 accB = make_float2(0.f, 0.f);
        int j = 0;
        for (; j + 1 < deg; j += 2) {
            float w0 = s_w[w][j],     w1 = s_w[w][j + 1];
            float2 v0 = __half22float2(h2[((size_t)s_src[w][j] << 5) + lane]);
            float2 v1 = __half22float2(h2[((size_t)s_src[w][j + 1] << 5) + lane]);
            acc.x  += w0 * v0.x;  acc.y  += w0 * v0.y;
            accB.x += w1 * v1.x;  accB.y += w1 * v1.y;
        }
        if (j < deg) {
            float wj = s_w[w][j];
            float2 v = __half22float2(h2[((size_t)s_src[w][j] << 5) + lane]);
            acc.x += wj * v.x;
            acc.y += wj * v.y;
        }
        acc.x += accB.x;
        acc.y += accB.y;
    } else {
        float m = aself;
        for (int e = start + lane; e < end; e += 32) {
            float a = as_[ssrc[e]] + adn;
            a = a > 0.f ? a : NEG_SLOPE * a;
            m = fmaxf(m, a);
        }
        #pragma unroll
        for (int o = 16; o; o >>= 1) m = fmaxf(m, __shfl_xor_sync(0xffffffffu, m, o));
        float wself = __expf(aself - m);
        float denl = (lane == 0) ? wself : 0.f;
        {
            float2 hs = __half22float2(h2[((size_t)node << 5) + lane]);
            acc.x = wself * hs.x;
            acc.y = wself * hs.y;
        }
        for (int eb = start; eb < end; eb += 32) {
            int e = eb + lane;
            float ex = 0.f; int s = 0;
            if (e < end) {
                s = ssrc[e];
                float a = as_[s] + adn;
                a = a > 0.f ? a : NEG_SLOPE * a;
                ex = __expf(a - m);
            }
            denl += ex;
            int cnt = min(32, end - eb);
            for (int j = 0; j < cnt; j++) {
                float wj = __shfl_sync(0xffffffffu, ex, j);
                int sj   = __shfl_sync(0xffffffffu, s, j);
                float2 v = __half22float2(h2[((size_t)sj << 5) + lane]);
                acc.x += wj * v.x;
                acc.y += wj * v.y;
            }
        }
        den = denl;
        #pragma unroll
        for (int o = 16; o; o >>= 1) den += __shfl_xor_sync(0xffffffffu, den, o);
    }

    float inv = 1.f / den;
    float2 b = ((const float2*)bias)[lane];
    float2 o2 = make_float2(acc.x * inv + b.x, acc.y * inv + b.y);
    ((float2*)out)[(size_t)node * 32 + lane] = o2;
    if (vntmp) {
        int blk = hb[node];
        atomicAdd(&vntmp[blk * H + lane * 2],     o2.x);
        atomicAdd(&vntmp[blk * H + lane * 2 + 1], o2.y);
    }
}

// ---------------- fused vn update + both MLPs ----------------
__global__ __launch_bounds__(256) void k_vn_mlp2(
    float* vn, const float* __restrict__ vn_tmp,
    const float* __restrict__ mw1, const float* __restrict__ mb1,
    const float* __restrict__ mw2, const float* __restrict__ mb2, int rows) {
    __shared__ __align__(16) float sW[H * H];
    __shared__ float sV[64 * 65];
    __shared__ float sRoot[H];
    __shared__ float sColNew[H];
    __shared__ float red[4][H];
    int t = threadIdx.x;
    int r0 = blockIdx.x * 64;

    if (t < H) sRoot[t] = vn[HNUM * H + t];
    __syncthreads();
    {
        int c = t & 63, g = t >> 6;
        float s = 0.f;
        for (int r = g; r < HNUM; r += 4) s += vn[r * H + c] + vn_tmp[r * H + c];
        red[g][c] = s;
    }
    __syncthreads();
    if (t < H) sColNew[t] = red[0][t] + red[1][t] + red[2][t] + red[3][t] + 257.f * sRoot[t];
    __syncthreads();
    for (int i = t; i < 64 * H; i += 256) {
        int r = i >> 6, c = i & 63;
        int gr = r0 + r;
        float val = 0.f;
        if (gr < HNUM)      val = vn[gr * H + c] + vn_tmp[gr * H + c] + sRoot[c];
        else if (gr == HNUM) val = sColNew[c];
        sV[r * 65 + c] = val;
    }
    int ty = t >> 4, tx = t & 15;
    for (int m = 0; m < 2; m++) {
        const float* w1 = mw1 + m * H * H;
        const float* b1 = mb1 + m * H;
        const float* w2 = mw2 + m * H * H;
        const float* b2 = mb2 + m * H;
        for (int i = t; i < H * H; i += 256) sW[i] = w1[i];
        __syncthreads();
        float acc[4][4] = {};
        #pragma unroll 8
        for (int k = 0; k < H; k++) {
            float a0 = sV[(ty * 4 + 0) * 65 + k];
            float a1 = sV[(ty * 4 + 1) * 65 + k];
            float a2 = sV[(ty * 4 + 2) * 65 + k];
            float a3 = sV[(ty * 4 + 3) * 65 + k];
            float4 w4 = *(const float4*)&sW[k * H + tx * 4];
            acc[0][0] += a0 * w4.x; acc[0][1] += a0 * w4.y; acc[0][2] += a0 * w4.z; acc[0][3] += a0 * w4.w;
            acc[1][0] += a1 * w4.x; acc[1][1] += a1 * w4.y; acc[1][2] += a1 * w4.z; acc[1][3] += a1 * w4.w;
            acc[2][0] += a2 * w4.x; acc[2][1] += a2 * w4.y; acc[2][2] += a2 * w4.z; acc[2][3] += a2 * w4.w;
            acc[3][0] += a3 * w4.x; acc[3][1] += a3 * w4.y; acc[3][2] += a3 * w4.z; acc[3][3] += a3 * w4.w;
        }
        __syncthreads();
        #pragma unroll
        for (int i = 0; i < 4; i++)
            #pragma unroll
            for (int j = 0; j < 4; j++) {
                float vbl = acc[i][j] + b1[tx * 4 + j];
                sV[(ty * 4 + i) * 65 + tx * 4 + j] = vbl > 0.f ? vbl : 0.f;
            }
        for (int i = t; i < H * H; i += 256) sW[i] = w2[i];
        __syncthreads();
        float acc2[4][4] = {};
        #pragma unroll 8
        for (int k = 0; k < H; k++) {
            float a0 = sV[(ty * 4 + 0) * 65 + k];
            float a1 = sV[(ty * 4 + 1) * 65 + k];
            float a2 = sV[(ty * 4 + 2) * 65 + k];
            float a3 = sV[(ty * 4 + 3) * 65 + k];
            float4 w4 = *(const float4*)&sW[k * H + tx * 4];
            acc2[0][0] += a0 * w4.x; acc2[0][1] += a0 * w4.y; acc2[0][2] += a0 * w4.z; acc2[0][3] += a0 * w4.w;
            acc2[1][0] += a1 * w4.x; acc2[1][1] += a1 * w4.y; acc2[1][2] += a1 * w4.z; acc2[1][3] += a1 * w4.w;
            acc2[2][0] += a2 * w4.x; acc2[2][1] += a2 * w4.y; acc2[2][2] += a2 * w4.z; acc2[2][3] += a2 * w4.w;
            acc2[3][0] += a3 * w4.x; acc2[3][1] += a3 * w4.y; acc2[3][2] += a3 * w4.z; acc2[3][3] += a3 * w4.w;
        }
        __syncthreads();
        #pragma unroll
        for (int i = 0; i < 4; i++)
            #pragma unroll
            for (int j = 0; j < 4; j++) {
                float vbl = acc2[i][j] + b2[tx * 4 + j];
                sV[(ty * 4 + i) * 65 + tx * 4 + j] = vbl > 0.f ? vbl : 0.f;
            }
        __syncthreads();
    }
    for (int i = t; i < 64 * H; i += 256) {
        int r = i >> 6, c = i & 63;
        if (r0 + r < rows) vn[(r0 + r) * H + c] = sV[r * 65 + c];
    }
}

// ---------------- host launch ----------------
extern "C" void kernel_launch(void* const* d_in, const int* in_sizes, int n_in,
                              void* d_out, int out_size) {
    const float* x  = (const float*)d_in[0];
    const int*   ei = (const int*)d_in[1];
    const int*   hb = (const int*)d_in[2];
    int base = (n_in >= 18) ? 5 : 4;
    const float* w_in     = (const float*)d_in[base + 0];
    const float* a_src_in = (const float*)d_in[base + 1];
    const float* a_dst_in = (const float*)d_in[base + 2];
    const float* b_in     = (const float*)d_in[base + 3];
    const float* w_l      = (const float*)d_in[base + 4];
    const float* a_src_l  = (const float*)d_in[base + 5];
    const float* a_dst_l  = (const float*)d_in[base + 6];
    const float* b_l      = (const float*)d_in[base + 7];
    const float* mw1      = (const float*)d_in[base + 8];
    const float* mb1      = (const float*)d_in[base + 9];
    const float* mw2      = (const float*)d_in[base + 10];
    const float* mb2      = (const float*)d_in[base + 11];
    const float* vne      = (const float*)d_in[base + 12];

    int N = in_sizes[0] / 3;
    int E = in_sizes[1] / 2;

    float *pout, *pas, *pad, *pas2, *pad2, *pvn, *pvntmp, *puv, *pwc, *pcc, *pps;
    float4* pxa;
    __half* ph;
    int *pdeg, *pst, *pen, *pcur, *pssrc, *ptotal;
    cudaGetSymbolAddress((void**)&ph, g_h);
    cudaGetSymbolAddress((void**)&pout, g_out);
    cudaGetSymbolAddress((void**)&pxa, g_xa);
    cudaGetSymbolAddress((void**)&pas, g_as);
    cudaGetSymbolAddress((void**)&pad, g_ad);
    cudaGetSymbolAddress((void**)&pas2, g_as2);
    cudaGetSymbolAddress((void**)&pad2, g_ad2);
    cudaGetSymbolAddress((void**)&pdeg, g_deg);
    cudaGetSymbolAddress((void**)&pst, g_st);
    cudaGetSymbolAddress((void**)&pen, g_en);
    cudaGetSymbolAddress((void**)&pcur, g_cur);
    cudaGetSymbolAddress((void**)&pssrc, g_ssrc);
    cudaGetSymbolAddress((void**)&ptotal, g_total);
    cudaGetSymbolAddress((void**)&pvn, g_vn);
    cudaGetSymbolAddress((void**)&pvntmp, g_vntmp);
    cudaGetSymbolAddress((void**)&puv, g_uv);
    cudaGetSymbolAddress((void**)&pwc, g_wc);
    cudaGetSymbolAddress((void**)&pcc, g_cc);
    cudaGetSymbolAddress((void**)&pps, g_ps);

    int nwarp_blocks = (N + 7) / 8;
    int gemm_blocks  = (N + 63) / 64;
    int nblocks_node = (N + 255) / 256;
    int nblocks_edge = (E + 255) / 256;
    int setup_blocks = 131 + nblocks_node + nblocks_edge;

    // 0: setup (hist + folded params + vn init + vntmp zero + packed xa/ad)
    k_setup<<<setup_blocks, 256>>>(x, ei, w_in, a_src_in, a_dst_in, b_in,
                                   w_l, a_src_l, a_dst_l,
                                   puv, pwc, pcc, pps,
                                   pvn, pvntmp, vne, pxa, pad, pdeg,
                                   ptotal, N, E, nblocks_node);
    // 1-2: CSR alloc + ILP-4 scatter
    k_alloc<<<nblocks_node, 256>>>(pdeg, pst, pen, pcur, ptotal, N);
    k_scatter<<<(E + 1023) / 1024, 256>>>(ei, pcur, pssrc, E);

    // 3: fused input GAT + layer-0 GEMM, quad-per-node online softmax, packed xa
    k_gat_in<<<(N + 63) / 64, 256>>>(pxa, pad, pst, pen, pssrc,
                                     pwc, pcc, pps, ph, pas2, pad2, N);
    // 4: layer-0 GAT (with fused vn segsum)
    k_gat<<<nwarp_blocks, 256>>>((const __half2*)ph, pas2, pad2, pst, pen, pssrc,
                                 b_l, pout, pvntmp, hb, N);
    // 5: fused vn update + both MLPs
    k_vn_mlp2<<<(HNUM + 1 + 63) / 64, 256>>>(pvn, pvntmp, mw1, mb1, mw2, mb2, HNUM + 1);

    // 6-7: l = 1 (trailing vn updates are dead code w.r.t. output)
    k_gemm64<<<gemm_blocks, 256>>>(pout, w_l + H * H, puv + 2 * H, puv + 3 * H,
                                   pvn, hb, ph, pas, pad, N);
    k_gat<<<nwarp_blocks, 256>>>((const __half2*)ph, pas, pad, pst, pen, pssrc,
                                 b_l + H, (float*)d_out, nullptr, nullptr, N);
}